// round 2
// baseline (speedup 1.0000x reference)
#include <cuda_runtime.h>
#include <cstdint>

typedef unsigned long long ull;

#define NB     16
#define DD     128
#define NENT   100000
#define NTILES 3125            // NENT / 32
#define XS_STRIDE 33           // float4 per staged row (32 + 1 pad -> conflict-free)
#define SMEM_BYTES ((NB*32 + 8*32*XS_STRIDE) * 16)   // hs4 (512 f4) + 8 warps * 1056 f4 = 143360 B

// ---------------- device scratch (allocation-free) ----------------
__device__ float    g_h[NB * DD];
__device__ float    g_sum[NB];
__device__ unsigned g_ctr;

// ---------------- packed f32x2 helpers (sm_103a) ----------------
__device__ __forceinline__ ull add2(ull a, ull b) {
    ull r; asm("add.rn.f32x2 %0,%1,%2;" : "=l"(r) : "l"(a), "l"(b)); return r;
}
__device__ __forceinline__ ull mul2(ull a, ull b) {
    ull r; asm("mul.rn.f32x2 %0,%1,%2;" : "=l"(r) : "l"(a), "l"(b)); return r;
}
__device__ __forceinline__ ull abs2(ull a) {
    return a & 0x7FFFFFFF7FFFFFFFull;
}
__device__ __forceinline__ ull pk2(float a, float b) {
    ull r; asm("mov.b64 %0,{%1,%2};" : "=l"(r) : "f"(a), "f"(b)); return r;
}
__device__ __forceinline__ float2 upk(ull a) {
    float2 f; asm("mov.b64 {%0,%1},%2;" : "=f"(f.x), "=f"(f.y) : "l"(a)); return f;
}
__device__ __forceinline__ float wsum(float v) {
    #pragma unroll
    for (int o = 16; o; o >>= 1) v += __shfl_xor_sync(0xffffffffu, v, o);
    return v;
}

// ---------------- kernel 1: init + h = norm(ent[e1]) + norm(rel[rel]) ----------------
__global__ void k_setup(const int* __restrict__ e1w, const int* __restrict__ relw,
                        const float* __restrict__ ent, const float* __restrict__ relemb) {
    __shared__ int s_is64;
    int tid = threadIdx.x;
    if (tid == 0) {
        // int64 detection: for int64 data the odd 32-bit words (high halves) are all 0.
        int o = e1w[1] | e1w[3] | e1w[5] | e1w[7] | e1w[9] | e1w[11] | e1w[13] | e1w[15];
        s_is64 = (o == 0);
        g_ctr = 0u;
    }
    if (tid < NB) g_sum[tid] = 0.0f;
    __syncthreads();

    int b = tid >> 5, l = tid & 31;     // 16 warps, warp b builds row b
    long long ei, ri;
    if (s_is64) {
        ei = ((const long long*)e1w)[b];
        ri = ((const long long*)relw)[b];
    } else {
        ei = (long long)e1w[b];
        ri = (long long)relw[b];
    }
    float4 a = ((const float4*)ent)[(size_t)ei * (DD/4) + l];
    float sa = wsum(fmaf(a.x, a.x, fmaf(a.y, a.y, fmaf(a.z, a.z, a.w * a.w))));
    float ia = rsqrtf(fmaxf(sa, 1e-24f));
    float4 c = ((const float4*)relemb)[(size_t)ri * (DD/4) + l];
    float sc = wsum(fmaf(c.x, c.x, fmaf(c.y, c.y, fmaf(c.z, c.z, c.w * c.w))));
    float ic = rsqrtf(fmaxf(sc, 1e-24f));
    float4 h;
    h.x = fmaf(a.x, ia, c.x * ic);
    h.y = fmaf(a.y, ia, c.y * ic);
    h.z = fmaf(a.z, ia, c.z * ic);
    h.w = fmaf(a.w, ia, c.w * ic);
    ((float4*)g_h)[b * (DD/4) + l] = h;
}

// ---------------- kernel 2: dist -> exp -> store + row sums ----------------
__global__ void __launch_bounds__(256)
k_dist(const float* __restrict__ ent, float* __restrict__ out) {
    extern __shared__ float4 sm4[];
    float4* hs4 = sm4;                                   // [16][32] float4 = h rows
    int tid = threadIdx.x, w = tid >> 5, l = tid & 31;
    float4* xs4 = sm4 + NB * 32 + w * (32 * XS_STRIDE);  // per-warp staging

    __shared__ float bsum[NB];
    if (tid < NB) bsum[tid] = 0.0f;
    #pragma unroll
    for (int i = tid; i < NB * 32; i += 256)
        hs4[i] = ((const float4*)g_h)[i];
    __syncthreads();

    float4* myrow = xs4 + l * XS_STRIDE;
    float myp = 0.0f;

    for (;;) {
        unsigned t = 0u;
        if (l == 0) t = atomicAdd(&g_ctr, 1u);
        t = __shfl_sync(0xffffffffu, t, 0);
        if (t >= (unsigned)NTILES) break;
        int base = (int)t * 32;
        const float4* rowp = (const float4*)ent + (size_t)base * 32 + l;

        __syncwarp();   // previous tile's reads done before overwriting xs
        // stage 32 entity rows, fully coalesced (512B per row per LDG wave)
        #pragma unroll
        for (int r0 = 0; r0 < 32; r0 += 8) {
            float4 v[8];
            #pragma unroll
            for (int r = 0; r < 8; r++) v[r] = rowp[(r0 + r) * 32];
            #pragma unroll
            for (int r = 0; r < 8; r++) xs4[(r0 + r) * XS_STRIDE + l] = v[r];
        }
        __syncwarp();

        // sumsq of my entity row (lane l owns entity base+l)
        float s0 = 0.f, s1 = 0.f, s2 = 0.f, s3 = 0.f;
        #pragma unroll
        for (int j = 0; j < 32; j += 4) {
            float4 v0 = myrow[j], v1 = myrow[j+1], v2 = myrow[j+2], v3 = myrow[j+3];
            s0 = fmaf(v0.x, v0.x, fmaf(v0.y, v0.y, fmaf(v0.z, v0.z, fmaf(v0.w, v0.w, s0))));
            s1 = fmaf(v1.x, v1.x, fmaf(v1.y, v1.y, fmaf(v1.z, v1.z, fmaf(v1.w, v1.w, s1))));
            s2 = fmaf(v2.x, v2.x, fmaf(v2.y, v2.y, fmaf(v2.z, v2.z, fmaf(v2.w, v2.w, s2))));
            s3 = fmaf(v3.x, v3.x, fmaf(v3.y, v3.y, fmaf(v3.z, v3.z, fmaf(v3.w, v3.w, s3))));
        }
        float ss  = (s0 + s1) + (s2 + s3);
        float inv = -rsqrtf(fmaxf(ss, 1e-24f));   // negated: h + (-x/|x|)
        ull ii = pk2(inv, inv);

        ull acc[NB];
        #pragma unroll
        for (int b = 0; b < NB; b++) acc[b] = 0ull;

        #pragma unroll 1
        for (int c = 0; c < 4; c++) {             // 4 chunks of 32 dims
            ull xr[16];
            #pragma unroll
            for (int jj = 0; jj < 8; jj++) {
                float4 v = myrow[c * 8 + jj];
                xr[2*jj]   = mul2(pk2(v.x, v.y), ii);
                xr[2*jj+1] = mul2(pk2(v.z, v.w), ii);
            }
            #pragma unroll
            for (int b = 0; b < NB; b++) {
                const float4* hp = hs4 + b * 32 + c * 8;   // uniform addr -> broadcast
                #pragma unroll
                for (int jj = 0; jj < 8; jj++) {
                    float4 hv = hp[jj];
                    acc[b] = add2(acc[b], abs2(add2(pk2(hv.x, hv.y), xr[2*jj])));
                    acc[b] = add2(acc[b], abs2(add2(pk2(hv.z, hv.w), xr[2*jj+1])));
                }
            }
        }

        // exp (no max subtraction needed: dist <= 3*sqrt(128) ~ 34, e^34 finite)
        #pragma unroll
        for (int b = 0; b < NB; b++) {
            float2 f = upk(acc[b]);
            float e = __expf(f.x + f.y);
            out[b * NENT + base + l] = e;          // coalesced per b
            float s = wsum(e);
            if (l == b) myp += s;                  // lane b keeps row b's partial
        }
    }

    if (l < NB) atomicAdd(&bsum[l], myp);
    __syncthreads();
    if (tid < NB) atomicAdd(&g_sum[tid], bsum[tid]);
}

// ---------------- kernel 3: pred = e / sum ----------------
__global__ void k_norm(float* __restrict__ out) {
    int b = blockIdx.y;
    float inv = 1.0f / g_sum[b];
    int i = blockIdx.x * blockDim.x + threadIdx.x;
    if (i < NENT / 4) {
        float4* o = (float4*)out + (size_t)b * (NENT / 4) + i;
        float4 v = *o;
        v.x *= inv; v.y *= inv; v.z *= inv; v.w *= inv;
        *o = v;
    }
}

// ---------------- launch ----------------
extern "C" void kernel_launch(void* const* d_in, const int* in_sizes, int n_in,
                              void* d_out, int out_size) {
    const int*   e1     = (const int*)d_in[0];
    const int*   rel    = (const int*)d_in[1];
    // d_in[2]=X, d_in[3]=A unused by forward
    const float* ent    = (const float*)d_in[4];
    const float* relemb = (const float*)d_in[5];
    float* out = (float*)d_out;

    cudaFuncSetAttribute(k_dist, cudaFuncAttributeMaxDynamicSharedMemorySize, SMEM_BYTES);

    k_setup<<<1, 512>>>(e1, rel, ent, relemb);
    k_dist<<<148, 256, SMEM_BYTES>>>(ent, out);
    dim3 gn((NENT / 4 + 255) / 256, NB);
    k_norm<<<gn, 256>>>(out);
    (void)in_sizes; (void)n_in; (void)out_size;
}